// round 11
// baseline (speedup 1.0000x reference)
#include <cuda_runtime.h>
#include <math.h>

#define L 512
#define NCON 20
#define INV_TEMP (1.0f / 0.07f)
#define SD_BLOCKS 1184  // 8 blocks/SM on 148 SMs -> 64 warps/SM (full occupancy)
#define SD_THREADS 256
#define WPB (SD_THREADS / 32)

// scratch (device globals; no allocation allowed)
__device__ float g_pB[SD_BLOCKS];        // per-block partials
__device__ unsigned int g_fin = 0;       // finalize counter (reset by last block)

// ---------------------------------------------------------------------------
// Single sample-driven kernel. Blocks [0,Bs) handle sz samples, [Bs,grid)
// handle nsz samples (branch uniform per block -> ONE ebar + ONE mask per
// block, minimal registers). One warp per sample, grid-stride over samples:
//   term_i = (log den_i - <row, ebar> * invnorm / tau) / Nbranch
// Row reads are coalesced (warp reads whole 2KB row); duplicate rows across
// samples hit L2. Deterministic: fixed per-warp sample sets, fixed-tree block
// reduction, fixed-order last-block finalize.
// ---------------------------------------------------------------------------
__global__ void __launch_bounds__(SD_THREADS, 8)
sample_kernel(const float* __restrict__ hg,
              const float* __restrict__ corr,
              const float* __restrict__ all_emb,
              const int* __restrict__ Psz, int nPsz,
              const int* __restrict__ Pnsz, int nPnsz,
              const int* __restrict__ sz_idx, int Ns,
              const int* __restrict__ nsz_idx, int Nn,
              int Bs, float invNs, float invNn,
              float* __restrict__ out) {
    __shared__ float se[L];
    __shared__ int sp[16];
    __shared__ float sw[WPB];
    __shared__ float sh[SD_THREADS];
    __shared__ bool is_last;

    int tid = threadIdx.x;
    int branch = (blockIdx.x >= Bs) ? 1 : 0;
    const int* P = branch ? Pnsz : Psz;
    int nP = branch ? nPnsz : nPsz;
    const int* idxp = branch ? nsz_idx : sz_idx;
    int count = branch ? Nn : Ns;
    float scale = branch ? invNn : invNs;

    if (tid < nP) sp[tid] = P[tid];
    __syncthreads();

    // exclusion bitmask for this branch (uniform)
    unsigned int mask = 0u;
    for (int j = 0; j < nP; j++) mask |= 1u << sp[j];

    // build this branch's ebar into smem (nP L2-hot concept rows)
    for (int t = tid; t < L; t += SD_THREADS) {
        float s = 0.0f;
        for (int j = 0; j < nP; j++) s += all_emb[sp[j] * L + t];
        se[t] = s / (float)nP;
    }
    __syncthreads();

    int lane = tid & 31;
    int wib  = tid >> 5;
    // warp index within this branch's block range, and branch warp count
    int bb = branch ? (blockIdx.x - Bs) : blockIdx.x;
    int nbb = branch ? (gridDim.x - Bs) : Bs;
    int wg = bb * WPB + wib;
    int nw = nbb * WPB;

    const float4* ep = reinterpret_cast<const float4*>(se);
    bool act = lane < NCON;
    float wm = (act && !((mask >> lane) & 1u)) ? 1.0f : 0.0f;

    float acc = 0.0f;
    int r = (wg < count) ? idxp[wg] : 0;   // prefetched index
    for (int i = wg; i < count; i += nw) {
        int rn = (i + nw < count) ? idxp[i + nw] : 0;  // prefetch next index

        // denominator: lanes 0..19 handle one concept each
        float e = act ? __expf(corr[r * NCON + lane] * INV_TEMP) : 0.0f;
        float den = e * wm;

        const float4* rp = reinterpret_cast<const float4*>(hg + (size_t)r * L);
        float ss = 0.0f, d = 0.0f;
#pragma unroll
        for (int it = 0; it < 4; it++) {
            int idx = it * 32 + lane;
            float4 v  = rp[idx];
            float4 ev = ep[idx];
            ss = fmaf(v.x, v.x, fmaf(v.y, v.y, fmaf(v.z, v.z, fmaf(v.w, v.w, ss))));
            d  = fmaf(v.x, ev.x, fmaf(v.y, ev.y, fmaf(v.z, ev.z, fmaf(v.w, ev.w, d))));
        }
#pragma unroll
        for (int o = 16; o > 0; o >>= 1) {
            ss  += __shfl_xor_sync(0xffffffffu, ss, o);
            d   += __shfl_xor_sync(0xffffffffu, d, o);
            den += __shfl_xor_sync(0xffffffffu, den, o);
        }
        if (lane == 0) {
            float invn = 1.0f / fmaxf(sqrtf(ss), 1e-12f);
            acc += (__logf(den) - d * invn * INV_TEMP) * scale;
        }
        r = rn;
    }

    // block partial + last-block fixed-order finalize
    if (lane == 0) sw[wib] = acc;
    __syncthreads();
    if (tid == 0) {
        float s = 0.0f;
#pragma unroll
        for (int k = 0; k < WPB; k++) s += sw[k];
        g_pB[blockIdx.x] = s;
        __threadfence();
        is_last = (atomicAdd(&g_fin, 1u) == gridDim.x - 1);
    }
    __syncthreads();

    if (is_last) {
        __threadfence();  // see all blocks' partials
        float a = 0.0f;
        for (int j = tid; j < SD_BLOCKS; j += SD_THREADS) a += g_pB[j];  // fixed order
        sh[tid] = a;
        __syncthreads();
        for (int s = 128; s > 0; s >>= 1) {
            if (tid < s) sh[tid] += sh[tid + s];
            __syncthreads();
        }
        if (tid == 0) { out[0] = sh[0]; g_fin = 0u; }
    }
}

extern "C" void kernel_launch(void* const* d_in, const int* in_sizes, int n_in,
                              void* d_out, int out_size) {
    const float* hg       = (const float*)d_in[0];
    const float* corr     = (const float*)d_in[1];
    const float* all_emb  = (const float*)d_in[2];
    const int*   sz_idx   = (const int*)d_in[3];
    const int*   nsz_idx  = (const int*)d_in[4];
    const int*   Psz_idx  = (const int*)d_in[5];
    const int*   Pnsz_idx = (const int*)d_in[6];
    float* out = (float*)d_out;

    int Ns    = in_sizes[3];
    int Nn    = in_sizes[4];
    int nPsz  = in_sizes[5];
    int nPnsz = in_sizes[6];

    // split blocks proportionally between branches
    long long tot = (long long)Ns + (long long)Nn;
    int Bs = (int)(((long long)SD_BLOCKS * Ns + tot - 1) / tot);
    if (Bs < 1) Bs = 1;
    if (Bs > SD_BLOCKS - 1) Bs = SD_BLOCKS - 1;

    sample_kernel<<<SD_BLOCKS, SD_THREADS>>>(hg, corr, all_emb,
                                             Psz_idx, nPsz, Pnsz_idx, nPnsz,
                                             sz_idx, Ns, nsz_idx, Nn,
                                             Bs, 1.0f / (float)Ns, 1.0f / (float)Nn,
                                             out);
}

// round 12
// speedup vs baseline: 1.1065x; 1.1065x over previous
#include <cuda_runtime.h>
#include <math.h>

#define L 512
#define NCON 20
#define INV_TEMP (1.0f / 0.07f)
#define SD_BLOCKS 592   // 4 blocks/SM on 148 SMs (proven best residency)
#define SD_THREADS 256
#define WPB (SD_THREADS / 32)

// scratch (device globals; no allocation allowed)
__device__ float g_pB[SD_BLOCKS];        // per-block partials
__device__ unsigned int g_fin = 0;       // finalize counter (reset by last block)

// ---------------------------------------------------------------------------
// Single sample-driven kernel, TWO samples per warp iteration (doubled MLP).
// Blocks [0,Bs) handle sz samples, [Bs,grid) handle nsz (branch uniform per
// block -> one ebar + one mask). Per pair: interleaved row loads (8 float4 in
// flight per lane), 6-value warp reduction, accumulate both terms.
//   term_i = (log den_i - <row_i, ebar> * invnorm_i / tau) / Nbranch
// Deterministic: fixed per-warp sample sets, fixed-tree reductions,
// fixed-order last-block finalize.
// ---------------------------------------------------------------------------
__global__ void __launch_bounds__(SD_THREADS)
sample_kernel(const float* __restrict__ hg,
              const float* __restrict__ corr,
              const float* __restrict__ all_emb,
              const int* __restrict__ Psz, int nPsz,
              const int* __restrict__ Pnsz, int nPnsz,
              const int* __restrict__ sz_idx, int Ns,
              const int* __restrict__ nsz_idx, int Nn,
              int Bs, float invNs, float invNn,
              float* __restrict__ out) {
    __shared__ float se[L];
    __shared__ int sp[16];
    __shared__ float sw[WPB];
    __shared__ float sh[SD_THREADS];
    __shared__ bool is_last;

    int tid = threadIdx.x;
    int branch = (blockIdx.x >= Bs) ? 1 : 0;
    const int* P = branch ? Pnsz : Psz;
    int nP = branch ? nPnsz : nPsz;
    const int* idxp = branch ? nsz_idx : sz_idx;
    int count = branch ? Nn : Ns;
    float scale = branch ? invNn : invNs;

    if (tid < nP) sp[tid] = P[tid];
    __syncthreads();

    // exclusion bitmask for this branch (uniform)
    unsigned int mask = 0u;
    for (int j = 0; j < nP; j++) mask |= 1u << sp[j];

    // build this branch's ebar into smem (nP L2-hot concept rows)
    for (int t = tid; t < L; t += SD_THREADS) {
        float s = 0.0f;
        for (int j = 0; j < nP; j++) s += all_emb[sp[j] * L + t];
        se[t] = s / (float)nP;
    }
    __syncthreads();

    int lane = tid & 31;
    int wib  = tid >> 5;
    int bb = branch ? (blockIdx.x - Bs) : blockIdx.x;
    int nbb = branch ? (gridDim.x - Bs) : Bs;
    int wg = bb * WPB + wib;     // warp index within branch
    int nw = nbb * WPB;          // warps in branch
    int stride = 2 * nw;

    const float4* ep = reinterpret_cast<const float4*>(se);
    bool act = lane < NCON;
    float wm = (act && !((mask >> lane) & 1u)) ? 1.0f : 0.0f;

    float acc = 0.0f;
    int i0 = 2 * wg;
    int ra = (i0 < count) ? idxp[i0] : 0;
    int rb = (i0 + 1 < count) ? idxp[i0 + 1] : ra;

    for (int i = i0; i < count; i += stride) {
        bool hasb = (i + 1 < count);
        // prefetch next pair's indices
        int na = (i + stride < count) ? idxp[i + stride] : 0;
        int nb = (i + stride + 1 < count) ? idxp[i + stride + 1] : na;

        // denominators: lanes 0..19 handle one concept each
        float ea = act ? __expf(corr[ra * NCON + lane] * INV_TEMP) : 0.0f;
        float eb = act ? __expf(corr[rb * NCON + lane] * INV_TEMP) : 0.0f;
        float dena = ea * wm;
        float denb = eb * wm;

        const float4* rpa = reinterpret_cast<const float4*>(hg + (size_t)ra * L);
        const float4* rpb = reinterpret_cast<const float4*>(hg + (size_t)rb * L);
        float ssa = 0.0f, da = 0.0f, ssb = 0.0f, db = 0.0f;
#pragma unroll
        for (int it = 0; it < 4; it++) {
            int idx = it * 32 + lane;
            float4 va = rpa[idx];
            float4 vb = rpb[idx];
            float4 ev = ep[idx];
            ssa = fmaf(va.x, va.x, fmaf(va.y, va.y, fmaf(va.z, va.z, fmaf(va.w, va.w, ssa))));
            da  = fmaf(va.x, ev.x, fmaf(va.y, ev.y, fmaf(va.z, ev.z, fmaf(va.w, ev.w, da))));
            ssb = fmaf(vb.x, vb.x, fmaf(vb.y, vb.y, fmaf(vb.z, vb.z, fmaf(vb.w, vb.w, ssb))));
            db  = fmaf(vb.x, ev.x, fmaf(vb.y, ev.y, fmaf(vb.z, ev.z, fmaf(vb.w, ev.w, db))));
        }
#pragma unroll
        for (int o = 16; o > 0; o >>= 1) {
            ssa  += __shfl_xor_sync(0xffffffffu, ssa, o);
            da   += __shfl_xor_sync(0xffffffffu, da, o);
            dena += __shfl_xor_sync(0xffffffffu, dena, o);
            ssb  += __shfl_xor_sync(0xffffffffu, ssb, o);
            db   += __shfl_xor_sync(0xffffffffu, db, o);
            denb += __shfl_xor_sync(0xffffffffu, denb, o);
        }
        if (lane == 0) {
            float invna = 1.0f / fmaxf(sqrtf(ssa), 1e-12f);
            acc += (__logf(dena) - da * invna * INV_TEMP) * scale;
            if (hasb) {
                float invnb = 1.0f / fmaxf(sqrtf(ssb), 1e-12f);
                acc += (__logf(denb) - db * invnb * INV_TEMP) * scale;
            }
        }
        ra = na;
        rb = nb;
    }

    // block partial + last-block fixed-order finalize
    if (lane == 0) sw[wib] = acc;
    __syncthreads();
    if (tid == 0) {
        float s = 0.0f;
#pragma unroll
        for (int k = 0; k < WPB; k++) s += sw[k];
        g_pB[blockIdx.x] = s;
        __threadfence();
        is_last = (atomicAdd(&g_fin, 1u) == gridDim.x - 1);
    }
    __syncthreads();

    if (is_last) {
        __threadfence();  // see all blocks' partials
        float a = 0.0f;
        for (int j = tid; j < SD_BLOCKS; j += SD_THREADS) a += g_pB[j];  // fixed order
        sh[tid] = a;
        __syncthreads();
        for (int s = 128; s > 0; s >>= 1) {
            if (tid < s) sh[tid] += sh[tid + s];
            __syncthreads();
        }
        if (tid == 0) { out[0] = sh[0]; g_fin = 0u; }
    }
}

extern "C" void kernel_launch(void* const* d_in, const int* in_sizes, int n_in,
                              void* d_out, int out_size) {
    const float* hg       = (const float*)d_in[0];
    const float* corr     = (const float*)d_in[1];
    const float* all_emb  = (const float*)d_in[2];
    const int*   sz_idx   = (const int*)d_in[3];
    const int*   nsz_idx  = (const int*)d_in[4];
    const int*   Psz_idx  = (const int*)d_in[5];
    const int*   Pnsz_idx = (const int*)d_in[6];
    float* out = (float*)d_out;

    int Ns    = in_sizes[3];
    int Nn    = in_sizes[4];
    int nPsz  = in_sizes[5];
    int nPnsz = in_sizes[6];

    // split blocks proportionally between branches
    long long tot = (long long)Ns + (long long)Nn;
    int Bs = (int)(((long long)SD_BLOCKS * Ns + tot - 1) / tot);
    if (Bs < 1) Bs = 1;
    if (Bs > SD_BLOCKS - 1) Bs = SD_BLOCKS - 1;

    sample_kernel<<<SD_BLOCKS, SD_THREADS>>>(hg, corr, all_emb,
                                             Psz_idx, nPsz, Pnsz_idx, nPnsz,
                                             sz_idx, Ns, nsz_idx, Nn,
                                             Bs, 1.0f / (float)Ns, 1.0f / (float)Nn,
                                             out);
}